// round 7
// baseline (speedup 1.0000x reference)
#include <cuda_runtime.h>
#include <cuda_fp16.h>
#include <cstdint>

#define N_NODES   100000
#define N_EDGES   600000
#define D_FEAT    128
#define NOUT      128          // 64 (P = h@Wu^T + b) + 64 (Q = h@Wv^T)
#define GRIDX     148
#define TILES     782          // ceil(N_NODES / 128)
#define EPB       128          // edges per gather block

// ---------------------------------------------------------------------------
// Device scratch: per-node projections in fp16.
// ---------------------------------------------------------------------------
__device__ __half g_PQh[(size_t)N_NODES * NOUT];

// Swizzled byte offset inside a [row][k] fp16 tile with 256B row stride.
__device__ __forceinline__ uint32_t tswz(int row, int kbyte) {
    return (uint32_t)(row * 256 + (kbyte ^ ((row & 7) << 4)));
}

__device__ __forceinline__ uint32_t smem_u32(const void* p) {
    uint32_t a;
    asm("{ .reg .u64 t; cvta.to.shared.u64 t, %1; cvt.u32.u64 %0, t; }" : "=r"(a) : "l"(p));
    return a;
}

__device__ __forceinline__ void ldsm_x4(uint32_t addr, uint32_t* r) {
    asm volatile("ldmatrix.sync.aligned.m8n8.x4.shared.b16 {%0,%1,%2,%3}, [%4];"
                 : "=r"(r[0]), "=r"(r[1]), "=r"(r[2]), "=r"(r[3]) : "r"(addr));
}
__device__ __forceinline__ void ldsm_x2(uint32_t addr, uint32_t* r) {
    asm volatile("ldmatrix.sync.aligned.m8n8.x2.shared.b16 {%0,%1}, [%2];"
                 : "=r"(r[0]), "=r"(r[1]) : "r"(addr));
}
__device__ __forceinline__ void mma_f16(float* c, const uint32_t* a, const uint32_t* b) {
    asm volatile("mma.sync.aligned.m16n8k16.row.col.f32.f16.f16.f32 "
                 "{%0,%1,%2,%3}, {%4,%5,%6,%7}, {%8,%9}, {%0,%1,%2,%3};"
                 : "+f"(c[0]), "+f"(c[1]), "+f"(c[2]), "+f"(c[3])
                 : "r"(a[0]), "r"(a[1]), "r"(a[2]), "r"(a[3]), "r"(b[0]), "r"(b[1]));
}

// Convert float4 -> 2x half2 and store 8B at swizzled offset.
__device__ __forceinline__ void f16_store(char* smem, uint32_t base,
                                          int row, int k4, float4 v) {
    __half2 h0 = __floats2half2_rn(v.x, v.y);
    __half2 h1 = __floats2half2_rn(v.z, v.w);
    uint32_t off = tswz(row, k4 * 8);
    *(uint2*)(smem + base + off) = make_uint2(*(uint32_t*)&h0, *(uint32_t*)&h1);
}

// ---------------------------------------------------------------------------
// Smem layout (GEMM): B once (fp16), A double-buffered (fp16).
// ---------------------------------------------------------------------------
#define SM_B     0u
#define SM_A0    32768u
#define SM_A1    65536u
#define SM_TOTAL 98304

// ---------------------------------------------------------------------------
// Kernel 1: persistent HMMA GEMM, single-pass fp16, fp32 accumulate.
// ---------------------------------------------------------------------------
__global__ void __launch_bounds__(256, 1)
gemm_kernel(const float* __restrict__ h, const float* __restrict__ W,
            const float* __restrict__ b) {
    extern __shared__ char smem[];
    const uint32_t sm_base = smem_u32(smem);
    const int tid = threadIdx.x;
    const int wid = tid >> 5;
    const int lid = tid & 31;

    // ---- Stage B once
    #pragma unroll
    for (int i = tid; i < 4096; i += 256) {
        int j  = i >> 5;
        int k4 = i & 31;
        const float* wp = (j < 64) ? &W[j * 256 + k4 * 4]
                                   : &W[(j - 64) * 256 + 128 + k4 * 4];
        f16_store(smem, SM_B, j, k4, *(const float4*)wp);
    }

    // ---- Stage A first tile into buf0
    {
        const int node0 = blockIdx.x * 128;
        #pragma unroll
        for (int i = 0; i < 16; ++i) {
            int idx = tid + i * 256;
            int m = idx >> 5, k4 = idx & 31;
            int gm = node0 + m; if (gm >= N_NODES) gm = N_NODES - 1;
            float4 v = *(const float4*)&h[(size_t)gm * D_FEAT + k4 * 4];
            f16_store(smem, SM_A0, m, k4, v);
        }
    }
    __syncthreads();

    const int wm = wid & 1;
    const int wn = wid >> 1;
    const int a_row = (lid & 7) + ((lid >> 3) & 1) * 8;
    const int a_kb  = (lid >> 4) * 16;
    const int b_row = (lid & 7);
    const int b_kb  = ((lid >> 3) & 1) * 16;
    const int xora  = (lid & 7) << 4;
    const int trow = lid >> 2;
    const int tcol = (lid & 3) * 2;

    float2 bias2[4];
    #pragma unroll
    for (int nf = 0; nf < 4; ++nf) {
        int col = wn * 32 + nf * 8 + tcol;
        bias2[nf] = (col < 64) ? *(const float2*)&b[col] : make_float2(0.f, 0.f);
    }

    int pb = 0;
    for (int t = blockIdx.x; t < TILES; t += GRIDX, pb ^= 1) {
        const int tn = t + GRIDX;
        const bool pre = (tn < TILES);

        float4 regs[16];
        if (pre) {
            const int node0n = tn * 128;
            #pragma unroll
            for (int i = 0; i < 16; ++i) {
                int idx = tid + i * 256;
                int m = idx >> 5, k4 = idx & 31;
                int gm = node0n + m; if (gm >= N_NODES) gm = N_NODES - 1;
                regs[i] = *(const float4*)&h[(size_t)gm * D_FEAT + k4 * 4];
            }
        }

        const uint32_t abase = sm_base + (pb ? SM_A1 : SM_A0);
        float acc[4][4][4];
        #pragma unroll
        for (int mf = 0; mf < 4; ++mf)
            #pragma unroll
            for (int nf = 0; nf < 4; ++nf)
                #pragma unroll
                for (int i = 0; i < 4; ++i) acc[mf][nf][i] = 0.0f;

        #pragma unroll
        for (int ks = 0; ks < 8; ++ks) {
            uint32_t af[4][4], bf[4][2];
            const uint32_t akoff = (uint32_t)((ks * 32 + a_kb) ^ xora);
            const uint32_t bkoff = (uint32_t)((ks * 32 + b_kb) ^ xora);
            #pragma unroll
            for (int mf = 0; mf < 4; ++mf) {
                uint32_t ro = (uint32_t)((wm * 64 + mf * 16 + a_row) * 256) + akoff;
                ldsm_x4(abase + ro, af[mf]);
            }
            #pragma unroll
            for (int nf = 0; nf < 4; ++nf) {
                uint32_t ro = (uint32_t)((wn * 32 + nf * 8 + b_row) * 256) + bkoff;
                ldsm_x2(sm_base + SM_B + ro, bf[nf]);
            }
            #pragma unroll
            for (int mf = 0; mf < 4; ++mf)
                #pragma unroll
                for (int nf = 0; nf < 4; ++nf)
                    mma_f16(acc[mf][nf], af[mf], bf[nf]);
        }

        if (pre) {
            const uint32_t obuf = pb ? SM_A0 : SM_A1;
            #pragma unroll
            for (int i = 0; i < 16; ++i) {
                int idx = tid + i * 256;
                int m = idx >> 5, k4 = idx & 31;
                f16_store(smem, obuf, m, k4, regs[i]);
            }
        }

        const int node0 = t * 128;
        #pragma unroll
        for (int mf = 0; mf < 4; ++mf) {
            const int node_a = node0 + wm * 64 + mf * 16 + trow;
            const int node_b = node_a + 8;
            #pragma unroll
            for (int nf = 0; nf < 4; ++nf) {
                const int col = wn * 32 + nf * 8 + tcol;
                if (node_a < N_NODES) {
                    __half2 hv = __floats2half2_rn(acc[mf][nf][0] + bias2[nf].x,
                                                   acc[mf][nf][1] + bias2[nf].y);
                    *(__half2*)&g_PQh[(size_t)node_a * NOUT + col] = hv;
                }
                if (node_b < N_NODES) {
                    __half2 hv = __floats2half2_rn(acc[mf][nf][2] + bias2[nf].x,
                                                   acc[mf][nf][3] + bias2[nf].y);
                    *(__half2*)&g_PQh[(size_t)node_b * NOUT + col] = hv;
                }
            }
        }
        __syncthreads();
    }
}

// ---------------------------------------------------------------------------
// Kernel 2: gather-add with smem staging + TMA bulk store (stores bypass L1).
// Block handles 128 consecutive edges; out region is one contiguous 32KB span.
// out[e][c] = PQh[src[e]][c] + PQh[dst[e]][64+c]
// ---------------------------------------------------------------------------
__global__ void __launch_bounds__(256)
gather_kernel(const int* __restrict__ src, const int* __restrict__ dst,
              float* __restrict__ out) {
    __shared__ __align__(16) float stage[EPB * 64];   // 32 KB

    const int tid = threadIdx.x;
    const int e0  = blockIdx.x * EPB;
    const int n   = (N_EDGES - e0 < EPB) ? (N_EDGES - e0) : EPB;

    #pragma unroll
    for (int i = 0; i < 4; ++i) {
        const int w  = tid + i * 256;       // 0..1023
        const int el = w >> 3;              // local edge 0..127
        const int q  = w & 7;               // 8-col chunk
        if (el < n) {
            const int e = e0 + el;
            unsigned int s = (unsigned int)__ldg(&src[e]);
            unsigned int d = (unsigned int)__ldg(&dst[e]);
            if (s >= N_NODES) s = 0;
            if (d >= N_NODES) d = 0;

            uint4 pv = *(const uint4*)&g_PQh[(size_t)s * NOUT + q * 8];
            uint4 rv = *(const uint4*)&g_PQh[(size_t)d * NOUT + 64 + q * 8];

            const __half2* ph = (const __half2*)&pv;
            const __half2* qh = (const __half2*)&rv;
            float o[8];
            #pragma unroll
            for (int j = 0; j < 4; ++j) {
                float2 a = __half22float2(ph[j]);
                float2 c = __half22float2(qh[j]);
                o[j * 2]     = a.x + c.x;
                o[j * 2 + 1] = a.y + c.y;
            }
            float* sp = &stage[el * 64 + q * 8];
            *(float4*)sp       = make_float4(o[0], o[1], o[2], o[3]);
            *(float4*)(sp + 4) = make_float4(o[4], o[5], o[6], o[7]);
        }
    }
    __syncthreads();

    if (tid == 0) {
        asm volatile("fence.proxy.async.shared::cta;" ::: "memory");
        const uint32_t saddr = smem_u32(stage);
        float* gaddr = out + (size_t)e0 * 64;
        const uint32_t bytes = (uint32_t)n * 256u;
        asm volatile("cp.async.bulk.global.shared::cta.bulk_group [%0], [%1], %2;"
                     :: "l"(gaddr), "r"(saddr), "r"(bytes) : "memory");
        asm volatile("cp.async.bulk.commit_group;" ::: "memory");
        asm volatile("cp.async.bulk.wait_group 0;" ::: "memory");
    }
}

// ---------------------------------------------------------------------------
extern "C" void kernel_launch(void* const* d_in, const int* in_sizes, int n_in,
                              void* d_out, int out_size) {
    const float* h   = (const float*)d_in[0];
    const int*   src = (const int*)  d_in[1];
    const int*   dst = (const int*)  d_in[2];
    const float* W   = (const float*)d_in[3];
    const float* b   = (const float*)d_in[4];
    float* out = (float*)d_out;

    cudaFuncSetAttribute(gemm_kernel, cudaFuncAttributeMaxDynamicSharedMemorySize, SM_TOTAL);

    gemm_kernel<<<GRIDX, 256, SM_TOTAL>>>(h, W, b);

    const int gblocks = (N_EDGES + EPB - 1) / EPB;   // 4688
    gather_kernel<<<gblocks, 256>>>(src, dst, out);
}

// round 8
// speedup vs baseline: 1.0310x; 1.0310x over previous
#include <cuda_runtime.h>
#include <cuda_fp16.h>
#include <cstdint>

#define N_NODES   100000
#define N_EDGES   600000
#define D_FEAT    128
#define NOUT      128          // 64 (P = h@Wu^T + b) + 64 (Q = h@Wv^T)
#define GRIDX     296          // 2 persistent CTAs per SM
#define TILES     782          // ceil(N_NODES / 128)

// ---------------------------------------------------------------------------
// Device scratch: per-node projections in fp16.
// ---------------------------------------------------------------------------
__device__ __half g_PQh[(size_t)N_NODES * NOUT];

// Swizzled byte offset inside a [row][k] fp16 tile with 256B row stride.
__device__ __forceinline__ uint32_t tswz(int row, int kbyte) {
    return (uint32_t)(row * 256 + (kbyte ^ ((row & 7) << 4)));
}

__device__ __forceinline__ uint32_t smem_u32(const void* p) {
    uint32_t a;
    asm("{ .reg .u64 t; cvta.to.shared.u64 t, %1; cvt.u32.u64 %0, t; }" : "=r"(a) : "l"(p));
    return a;
}

__device__ __forceinline__ void ldsm_x4(uint32_t addr, uint32_t* r) {
    asm volatile("ldmatrix.sync.aligned.m8n8.x4.shared.b16 {%0,%1,%2,%3}, [%4];"
                 : "=r"(r[0]), "=r"(r[1]), "=r"(r[2]), "=r"(r[3]) : "r"(addr));
}
__device__ __forceinline__ void ldsm_x2(uint32_t addr, uint32_t* r) {
    asm volatile("ldmatrix.sync.aligned.m8n8.x2.shared.b16 {%0,%1}, [%2];"
                 : "=r"(r[0]), "=r"(r[1]) : "r"(addr));
}
__device__ __forceinline__ void mma_f16(float* c, const uint32_t* a, const uint32_t* b) {
    asm volatile("mma.sync.aligned.m16n8k16.row.col.f32.f16.f16.f32 "
                 "{%0,%1,%2,%3}, {%4,%5,%6,%7}, {%8,%9}, {%0,%1,%2,%3};"
                 : "+f"(c[0]), "+f"(c[1]), "+f"(c[2]), "+f"(c[3])
                 : "r"(a[0]), "r"(a[1]), "r"(a[2]), "r"(a[3]), "r"(b[0]), "r"(b[1]));
}

// Convert float4 -> 2x half2 and store 8B at swizzled offset.
__device__ __forceinline__ void f16_store(char* smem, uint32_t base,
                                          int row, int k4, float4 v) {
    __half2 h0 = __floats2half2_rn(v.x, v.y);
    __half2 h1 = __floats2half2_rn(v.z, v.w);
    uint32_t off = tswz(row, k4 * 8);
    *(uint2*)(smem + base + off) = make_uint2(*(uint32_t*)&h0, *(uint32_t*)&h1);
}

// ---------------------------------------------------------------------------
// Smem layout (GEMM): B once (fp16), single A buffer (fp16). 64 KB total
// -> 2 CTAs resident per SM for cross-CTA staging/MMA overlap.
// ---------------------------------------------------------------------------
#define SM_B     0u
#define SM_A     32768u
#define SM_TOTAL 65536

// ---------------------------------------------------------------------------
// Kernel 1: persistent HMMA GEMM, single-pass fp16, fp32 accumulate.
// 296 CTAs (2/SM); W staged once per CTA; A single-buffered (overlap comes
// from the co-resident CTA, not intra-CTA pipelining).
// ---------------------------------------------------------------------------
__global__ void __launch_bounds__(256, 2)
gemm_kernel(const float* __restrict__ h, const float* __restrict__ W,
            const float* __restrict__ b) {
    extern __shared__ char smem[];
    const uint32_t sm_base = smem_u32(smem);
    const int tid = threadIdx.x;
    const int wid = tid >> 5;
    const int lid = tid & 31;

    // ---- Stage B once
    #pragma unroll
    for (int i = tid; i < 4096; i += 256) {
        int j  = i >> 5;
        int k4 = i & 31;
        const float* wp = (j < 64) ? &W[j * 256 + k4 * 4]
                                   : &W[(j - 64) * 256 + 128 + k4 * 4];
        f16_store(smem, SM_B, j, k4, *(const float4*)wp);
    }

    const int wm = wid & 1;
    const int wn = wid >> 1;
    const int a_row = (lid & 7) + ((lid >> 3) & 1) * 8;
    const int a_kb  = (lid >> 4) * 16;
    const int b_row = (lid & 7);
    const int b_kb  = ((lid >> 3) & 1) * 16;
    const int xora  = (lid & 7) << 4;
    const int trow = lid >> 2;
    const int tcol = (lid & 3) * 2;

    float2 bias2[4];
    #pragma unroll
    for (int nf = 0; nf < 4; ++nf) {
        int col = wn * 32 + nf * 8 + tcol;
        bias2[nf] = (col < 64) ? *(const float2*)&b[col] : make_float2(0.f, 0.f);
    }

    for (int t = blockIdx.x; t < TILES; t += GRIDX) {
        // ---- Stage A for this tile (A buffer free: previous iter ended in sync)
        const int node0 = t * 128;
        #pragma unroll
        for (int i = 0; i < 16; ++i) {
            int idx = tid + i * 256;
            int m = idx >> 5, k4 = idx & 31;
            int gm = node0 + m; if (gm >= N_NODES) gm = N_NODES - 1;
            float4 v = *(const float4*)&h[(size_t)gm * D_FEAT + k4 * 4];
            f16_store(smem, SM_A, m, k4, v);
        }
        __syncthreads();

        // ---- MMA mainloop
        float acc[4][4][4];
        #pragma unroll
        for (int mf = 0; mf < 4; ++mf)
            #pragma unroll
            for (int nf = 0; nf < 4; ++nf)
                #pragma unroll
                for (int i = 0; i < 4; ++i) acc[mf][nf][i] = 0.0f;

        #pragma unroll
        for (int ks = 0; ks < 8; ++ks) {
            uint32_t af[4][4], bf[4][2];
            const uint32_t akoff = (uint32_t)((ks * 32 + a_kb) ^ xora);
            const uint32_t bkoff = (uint32_t)((ks * 32 + b_kb) ^ xora);
            #pragma unroll
            for (int mf = 0; mf < 4; ++mf) {
                uint32_t ro = (uint32_t)((wm * 64 + mf * 16 + a_row) * 256) + akoff;
                ldsm_x4(sm_base + SM_A + ro, af[mf]);
            }
            #pragma unroll
            for (int nf = 0; nf < 4; ++nf) {
                uint32_t ro = (uint32_t)((wn * 32 + nf * 8 + b_row) * 256) + bkoff;
                ldsm_x2(sm_base + SM_B + ro, bf[nf]);
            }
            #pragma unroll
            for (int mf = 0; mf < 4; ++mf)
                #pragma unroll
                for (int nf = 0; nf < 4; ++nf)
                    mma_f16(acc[mf][nf], af[mf], bf[nf]);
        }

        // ---- Epilogue: bias + fp16 store to PQ
        #pragma unroll
        for (int mf = 0; mf < 4; ++mf) {
            const int node_a = node0 + wm * 64 + mf * 16 + trow;
            const int node_b = node_a + 8;
            #pragma unroll
            for (int nf = 0; nf < 4; ++nf) {
                const int col = wn * 32 + nf * 8 + tcol;
                if (node_a < N_NODES) {
                    __half2 hv = __floats2half2_rn(acc[mf][nf][0] + bias2[nf].x,
                                                   acc[mf][nf][1] + bias2[nf].y);
                    *(__half2*)&g_PQh[(size_t)node_a * NOUT + col] = hv;
                }
                if (node_b < N_NODES) {
                    __half2 hv = __floats2half2_rn(acc[mf][nf][2] + bias2[nf].x,
                                                   acc[mf][nf][3] + bias2[nf].y);
                    *(__half2*)&g_PQh[(size_t)node_b * NOUT + col] = hv;
                }
            }
        }
        __syncthreads();   // A buffer reusable next iteration
    }
}

// ---------------------------------------------------------------------------
// Kernel 2: gather-add, 2 edges per thread (R6 formulation — best measured).
// out[e][c] = PQh[src[e]][c] + PQh[dst[e]][64+c]
// ---------------------------------------------------------------------------
__global__ void __launch_bounds__(256)
gather_kernel(const int* __restrict__ src, const int* __restrict__ dst,
              float* __restrict__ out) {
    int t = blockIdx.x * blockDim.x + threadIdx.x;
    if (t >= (N_EDGES / 2) * 8) return;
    const int ep = t >> 3;
    const int q  = t & 7;
    const int e0 = ep * 2;
    const int e1 = e0 + 1;

    unsigned int s0 = (unsigned int)__ldg(&src[e0]);
    unsigned int d0 = (unsigned int)__ldg(&dst[e0]);
    unsigned int s1 = (unsigned int)__ldg(&src[e1]);
    unsigned int d1 = (unsigned int)__ldg(&dst[e1]);
    if (s0 >= N_NODES) s0 = 0;
    if (d0 >= N_NODES) d0 = 0;
    if (s1 >= N_NODES) s1 = 0;
    if (d1 >= N_NODES) d1 = 0;

    uint4 p0 = *(const uint4*)&g_PQh[(size_t)s0 * NOUT + q * 8];
    uint4 r0 = *(const uint4*)&g_PQh[(size_t)d0 * NOUT + 64 + q * 8];
    uint4 p1 = *(const uint4*)&g_PQh[(size_t)s1 * NOUT + q * 8];
    uint4 r1 = *(const uint4*)&g_PQh[(size_t)d1 * NOUT + 64 + q * 8];

    float o0[8], o1[8];
    {
        const __half2* ph = (const __half2*)&p0;
        const __half2* qh = (const __half2*)&r0;
        #pragma unroll
        for (int i = 0; i < 4; ++i) {
            float2 a = __half22float2(ph[i]);
            float2 c = __half22float2(qh[i]);
            o0[i * 2] = a.x + c.x; o0[i * 2 + 1] = a.y + c.y;
        }
    }
    {
        const __half2* ph = (const __half2*)&p1;
        const __half2* qh = (const __half2*)&r1;
        #pragma unroll
        for (int i = 0; i < 4; ++i) {
            float2 a = __half22float2(ph[i]);
            float2 c = __half22float2(qh[i]);
            o1[i * 2] = a.x + c.x; o1[i * 2 + 1] = a.y + c.y;
        }
    }

    float* op0 = out + (size_t)e0 * 64 + q * 8;
    float* op1 = out + (size_t)e1 * 64 + q * 8;
    __stcs((float4*)op0,     make_float4(o0[0], o0[1], o0[2], o0[3]));
    __stcs((float4*)op0 + 1, make_float4(o0[4], o0[5], o0[6], o0[7]));
    __stcs((float4*)op1,     make_float4(o1[0], o1[1], o1[2], o1[3]));
    __stcs((float4*)op1 + 1, make_float4(o1[4], o1[5], o1[6], o1[7]));
}

// ---------------------------------------------------------------------------
extern "C" void kernel_launch(void* const* d_in, const int* in_sizes, int n_in,
                              void* d_out, int out_size) {
    const float* h   = (const float*)d_in[0];
    const int*   src = (const int*)  d_in[1];
    const int*   dst = (const int*)  d_in[2];
    const float* W   = (const float*)d_in[3];
    const float* b   = (const float*)d_in[4];
    float* out = (float*)d_out;

    cudaFuncSetAttribute(gemm_kernel, cudaFuncAttributeMaxDynamicSharedMemorySize, SM_TOTAL);

    gemm_kernel<<<GRIDX, 256, SM_TOTAL>>>(h, W, b);

    const int gthreads = (N_EDGES / 2) * 8;   // 2.4M
    gather_kernel<<<(gthreads + 255) / 256, 256>>>(src, dst, out);
}